// round 9
// baseline (speedup 1.0000x reference)
#include <cuda_runtime.h>
#include <cuda_bf16.h>

#define FULLMASK 0xffffffffu

__device__ float g_losses[256];

// One CTA = 128 threads = 4 warps (1 per SMSP), occ 1, grid B/2 = 128.
// Thread c owns column c of TWO batches (2*bid, 2*bid+1). Both batches share
// the same register-resident expT column (T[64] bf16x2). The two per-step
// dependency streams (dot/tail for A, dot/tail for B) are independent, so the
// warp hides its own serial tail via ILP -- no partner warp, no barrier games.
__global__ void __launch_bounds__(128, 1) k_crf_forward(
    const float* __restrict__ feats,   // [B,S,L]
    const float* __restrict__ startT,  // [L]
    const float* __restrict__ endT,    // [L]
    const float* __restrict__ trans,   // [L,L]
    const float* __restrict__ conf,    // [B]
    const int*   __restrict__ mask,    // [B,S]
    const int*   __restrict__ labels,  // [B,S]
    int S)
{
    constexpr int L = 128;
    extern __shared__ char sm[];
    char*  ebA   = sm;                                  // [2][128] bf16 = 512B
    char*  ebB   = sm + 512;                            // [2][128] bf16 = 512B
    int*   smA   = (int*)(sm + 1024);                   // [S]
    int*   smB   = (int*)(sm + 1024 + S * 4);           // [S]
    float* sred  = (float*)(sm + 1024 + 2 * S * 4);     // [16]

    const int c   = threadIdx.x;       // owned column
    const int wid = c >> 5;            // warp 0..3
    const int bA  = 2 * blockIdx.x;
    const int bB  = bA + 1;

    const float* fa = feats + (size_t)bA * S * L;
    const float* fbp = feats + (size_t)bB * S * L;

    // ---- expT column c into registers (shared by both batches) ----
    __nv_bfloat162 T[64];
    #pragma unroll
    for (int k = 0; k < 64; ++k) {
        float t0 = __expf(__ldg(trans + (size_t)(2 * k) * L + c));
        float t1 = __expf(__ldg(trans + (size_t)(2 * k + 1) * L + c));
        T[k] = __floats2bfloat162_rn(t0, t1);
    }
    for (int k = c; k < S; k += 128) {
        smA[k] = mask[bA * S + k];
        smB[k] = mask[bB * S + k];
    }

    // ---- alpha0 for both batches ----
    float aA = startT[c] + fa[c];
    float aB = startT[c] + fbp[c];
    __syncthreads();                       // masks ready
    float mvA = aA, mvB = aB;
    #pragma unroll
    for (int o = 16; o; o >>= 1) {
        mvA = fmaxf(mvA, __shfl_xor_sync(FULLMASK, mvA, o));
        mvB = fmaxf(mvB, __shfl_xor_sync(FULLMASK, mvB, o));
    }
    if ((c & 31) == 0) { sred[wid] = mvA; sred[4 + wid] = mvB; }
    __syncthreads();
    float mA = fmaxf(fmaxf(sred[0], sred[1]), fmaxf(sred[2], sred[3]));
    float mB = fmaxf(fmaxf(sred[4], sred[5]), fmaxf(sred[6], sred[7]));

    float vA = __expf(aA - mA), vB = __expf(aB - mB);
    float offA = mA, offB = mB;            // alpha = off + log(v)
    *(__nv_bfloat16*)(ebA + 256 + 2 * c) = __float2bfloat16(vA);  // phase 1
    *(__nv_bfloat16*)(ebB + 256 + 2 * c) = __float2bfloat16(vB);

    float fA1 = fa[L + c];
    float fA2 = (S > 2) ? fa[2 * (size_t)L + c] : 0.f;
    float fB1 = fbp[L + c];
    float fB2 = (S > 2) ? fbp[2 * (size_t)L + c] : 0.f;
    __syncthreads();

    const __nv_bfloat162 bz = __floats2bfloat162_rn(0.f, 0.f);

    for (int t = 1; t < S; ++t) {
        const uint4* seA = (const uint4*)(ebA + (t & 1) * 256);
        const uint4* seB = (const uint4*)(ebB + (t & 1) * 256);
        char* wbA = ebA + ((t & 1) ^ 1) * 256;
        char* wbB = ebB + ((t & 1) ^ 1) * 256;

        __nv_bfloat162 a0 = bz, a1 = bz, a2 = bz, a3 = bz;   // batch A chains
        __nv_bfloat162 b0 = bz, b1 = bz, b2 = bz, b3 = bz;   // batch B chains
        float e0A = 1.0f, e0B = 1.0f;
        #pragma unroll
        for (int p = 0; p < 16; ++p) {
            uint4 qa = seA[p];                    // A: e[8p..8p+7]
            uint4 qb = seB[p];                    // B: e[8p..8p+7]
            __nv_bfloat162 qa0 = *(__nv_bfloat162*)&qa.x;
            __nv_bfloat162 qa1 = *(__nv_bfloat162*)&qa.y;
            __nv_bfloat162 qa2 = *(__nv_bfloat162*)&qa.z;
            __nv_bfloat162 qa3 = *(__nv_bfloat162*)&qa.w;
            __nv_bfloat162 qb0 = *(__nv_bfloat162*)&qb.x;
            __nv_bfloat162 qb1 = *(__nv_bfloat162*)&qb.y;
            __nv_bfloat162 qb2 = *(__nv_bfloat162*)&qb.z;
            __nv_bfloat162 qb3 = *(__nv_bfloat162*)&qb.w;
            if (p == 0) { e0A = __low2float(qa0); e0B = __low2float(qb0); }
            a0 = __hfma2(qa0, T[4 * p + 0], a0);
            b0 = __hfma2(qb0, T[4 * p + 0], b0);
            a1 = __hfma2(qa1, T[4 * p + 1], a1);
            b1 = __hfma2(qb1, T[4 * p + 1], b1);
            a2 = __hfma2(qa2, T[4 * p + 2], a2);
            b2 = __hfma2(qb2, T[4 * p + 2], b2);
            a3 = __hfma2(qa3, T[4 * p + 3], a3);
            b3 = __hfma2(qb3, T[4 * p + 3], b3);
        }
        a0 = __hadd2(a0, a1); a2 = __hadd2(a2, a3); a0 = __hadd2(a0, a2);
        b0 = __hadd2(b0, b1); b2 = __hadd2(b2, b3); b0 = __hadd2(b0, b2);
        float sA = __low2float(a0) + __high2float(a0);
        float sB = __low2float(b0) + __high2float(b0);

        float fcA = fA1, fcB = fB1;
        fA1 = fA2; fB1 = fB2;
        if (t + 2 < S) {
            fA2 = fa[(size_t)(t + 2) * L + c];
            fB2 = fbp[(size_t)(t + 2) * L + c];
        }

        if (smA[t]) {
            vA = sA * __expf(fcA);
            if ((t & 3) == 0) { vA *= __frcp_rn(e0A); offA += __logf(e0A); }
        }
        if (smB[t]) {
            vB = sB * __expf(fcB);
            if ((t & 3) == 0) { vB *= __frcp_rn(e0B); offB += __logf(e0B); }
        }

        *(__nv_bfloat16*)(wbA + 2 * c) = __float2bfloat16(vA);
        *(__nv_bfloat16*)(wbB + 2 * c) = __float2bfloat16(vB);
        __syncthreads();
    }

    // ---- denominators ----
    float eend = __expf(endT[c]);
    float cA = vA * eend, cB = vB * eend;
    #pragma unroll
    for (int o = 16; o; o >>= 1) {
        cA += __shfl_xor_sync(FULLMASK, cA, o);
        cB += __shfl_xor_sync(FULLMASK, cB, o);
    }
    if ((c & 31) == 0) { sred[wid] = cA; sred[4 + wid] = cB; }
    __syncthreads();
    float log_denA = offA + __logf((sred[0] + sred[1]) + (sred[2] + sred[3]));
    float log_denB = offB + __logf((sred[4] + sred[5]) + (sred[6] + sred[7]));
    __syncthreads();

    // ---- numerators (exact fp32) ----
    float numA = 0.f, slfA = 0.f, numB = 0.f, slfB = 0.f;
    const int* lbA = labels + bA * S;
    const int* lbB = labels + bB * S;
    for (int k = c; k < S; k += 128) {
        int mkA = smA[k], mkB = smB[k];
        slfA += (float)mkA; slfB += (float)mkB;
        int laA = lbA[k]; if (laA == -100) laA = 0;
        int laB = lbB[k]; if (laB == -100) laB = 0;
        if (k == 0) {
            numA += startT[laA] + fa[laA];
            numB += startT[laB] + fbp[laB];
        } else {
            if (mkA) {
                int lp = lbA[k - 1]; if (lp == -100) lp = 0;
                numA += trans[lp * L + laA] + fa[(size_t)k * L + laA];
            }
            if (mkB) {
                int lp = lbB[k - 1]; if (lp == -100) lp = 0;
                numB += trans[lp * L + laB] + fbp[(size_t)k * L + laB];
            }
        }
    }
    #pragma unroll
    for (int o = 16; o; o >>= 1) {
        numA += __shfl_xor_sync(FULLMASK, numA, o);
        numB += __shfl_xor_sync(FULLMASK, numB, o);
        slfA += __shfl_xor_sync(FULLMASK, slfA, o);
        slfB += __shfl_xor_sync(FULLMASK, slfB, o);
    }
    if ((c & 31) == 0) {
        sred[wid] = numA; sred[4 + wid] = numB;
        sred[8 + wid] = slfA; sred[12 + wid] = slfB;
    }
    __syncthreads();
    numA = (sred[0] + sred[1]) + (sred[2] + sred[3]);
    numB = (sred[4] + sred[5]) + (sred[6] + sred[7]);
    slfA = (sred[8] + sred[9]) + (sred[10] + sred[11]);
    slfB = (sred[12] + sred[13]) + (sred[14] + sred[15]);

    int ltA = (int)(slfA + 0.5f) - 1; if (ltA < 0) ltA = 0;
    int ltB = (int)(slfB + 0.5f) - 1; if (ltB < 0) ltB = 0;
    int llA = lbA[ltA]; if (llA == -100) llA = 0;
    int llB = lbB[ltB]; if (llB == -100) llB = 0;
    numA += endT[llA];
    numB += endT[llB];

    if (c == 0) {
        g_losses[bA] = (log_denA - numA) * conf[bA];
        g_losses[bB] = (log_denB - numB) * conf[bB];
    }
}

__global__ void k_finalize(float* __restrict__ out, int B) {
    int t = threadIdx.x;
    float x = (t < B) ? g_losses[t] : 0.f;
    #pragma unroll
    for (int o = 16; o; o >>= 1) x += __shfl_xor_sync(FULLMASK, x, o);
    __shared__ float sh[8];
    if ((t & 31) == 0) sh[t >> 5] = x;
    __syncthreads();
    if (t == 0) {
        float s = 0.f;
        int nw = (blockDim.x + 31) >> 5;
        for (int w = 0; w < nw; ++w) s += sh[w];
        out[0] = s / (float)B;
    }
}

extern "C" void kernel_launch(void* const* d_in, const int* in_sizes, int n_in,
                              void* d_out, int out_size) {
    const float* feats  = (const float*)d_in[0];
    const float* startT = (const float*)d_in[1];
    const float* endT   = (const float*)d_in[2];
    const float* trans  = (const float*)d_in[3];
    const float* conf   = (const float*)d_in[4];
    const int*   mask   = (const int*)  d_in[5];
    const int*   labels = (const int*)  d_in[6];

    const int B = in_sizes[4];            // 256
    const int S = in_sizes[5] / B;        // 512
    (void)n_in; (void)out_size;

    size_t smem = 1024                    // 2 batches x double-buffered e vecs
                + (size_t)2 * S * 4       // masks
                + 64;                     // reduction scratch

    k_crf_forward<<<B / 2, 128, smem>>>(feats, startT, endT, trans, conf,
                                        mask, labels, S);
    k_finalize<<<1, 256>>>((float*)d_out, B);
}

// round 10
// speedup vs baseline: 1.2079x; 1.2079x over previous
#include <cuda_runtime.h>
#include <cuda_bf16.h>

#define FULLMASK 0xffffffffu

__device__ float g_losses[256];

// One CTA = ONE batch = 128 threads = 4 warps (one per SMSP).
// Occupancy 2, grid 256: every SMSP holds 2 warps from INDEPENDENT CTAs
// (separate bar-0 domains), so they drift out of phase and hide each
// other's per-step serial tails -- the r5 mechanism, on all 4 SMSPs.
// Thread owns ONE column c: 64 bf16x2 expT regs, 64 HFMA2/step.
__global__ void __launch_bounds__(128, 2) k_crf_forward(
    const float* __restrict__ feats,   // [B,S,L]
    const float* __restrict__ startT,  // [L]
    const float* __restrict__ endT,    // [L]
    const float* __restrict__ trans,   // [L,L]
    const float* __restrict__ conf,    // [B]
    const int*   __restrict__ mask,    // [B,S]
    const int*   __restrict__ labels,  // [B,S]
    int S)
{
    constexpr int L = 128;
    extern __shared__ char sm[];
    char*  ebuf  = sm;                             // [2][128] bf16 = 512B
    int*   smask = (int*)(sm + 512);               // [S]
    float* sred  = (float*)(sm + 512 + S * 4);     // [8]

    const int c   = threadIdx.x;       // owned column
    const int wid = c >> 5;            // warp 0..3
    const int b   = blockIdx.x;

    const float* fb = feats + (size_t)b * S * L;

    // ---- expT column c into registers: 64 bf16x2 (i-pairs) ----
    __nv_bfloat162 T[64];
    #pragma unroll
    for (int k = 0; k < 64; ++k) {
        float t0 = __expf(__ldg(trans + (size_t)(2 * k) * L + c));
        float t1 = __expf(__ldg(trans + (size_t)(2 * k + 1) * L + c));
        T[k] = __floats2bfloat162_rn(t0, t1);
    }
    for (int k = c; k < S; k += 128) smask[k] = mask[b * S + k];

    // ---- alpha0 ----
    float a0 = startT[c] + fb[c];
    __syncthreads();                       // smask ready
    float mv = a0;
    #pragma unroll
    for (int o = 16; o; o >>= 1) mv = fmaxf(mv, __shfl_xor_sync(FULLMASK, mv, o));
    if ((c & 31) == 0) sred[wid] = mv;
    __syncthreads();
    float m0 = fmaxf(fmaxf(sred[0], sred[1]), fmaxf(sred[2], sred[3]));

    float v = __expf(a0 - m0);             // exp-domain alpha, normalized
    float offset = m0;                     // alpha = offset + log(v)
    *(__nv_bfloat16*)(ebuf + 256 + 2 * c) = __float2bfloat16(v);  // phase 1

    float fA = fb[L + c];                              // feat(t=1)
    float fB = (S > 2) ? fb[2 * (size_t)L + c] : 0.f;  // feat(t=2)
    __syncthreads();

    const __nv_bfloat162 bz = __floats2bfloat162_rn(0.f, 0.f);

    for (int t = 1; t < S; ++t) {
        const uint4* se = (const uint4*)(ebuf + (t & 1) * 256);   // read phase
        char*        wb = ebuf + ((t & 1) ^ 1) * 256;             // write phase

        __nv_bfloat162 acc0 = bz, acc1 = bz, acc2 = bz, acc3 = bz;
        float e0f = 1.0f;
        #pragma unroll
        for (int p = 0; p < 16; ++p) {
            uint4 q = se[p];                       // e[8p .. 8p+7]
            __nv_bfloat162 q0 = *(__nv_bfloat162*)&q.x;
            __nv_bfloat162 q1 = *(__nv_bfloat162*)&q.y;
            __nv_bfloat162 q2 = *(__nv_bfloat162*)&q.z;
            __nv_bfloat162 q3 = *(__nv_bfloat162*)&q.w;
            if (p == 0) e0f = __low2float(q0);     // e[0]: free normalizer
            acc0 = __hfma2(q0, T[4 * p + 0], acc0);
            acc1 = __hfma2(q1, T[4 * p + 1], acc1);
            acc2 = __hfma2(q2, T[4 * p + 2], acc2);
            acc3 = __hfma2(q3, T[4 * p + 3], acc3);
        }
        acc0 = __hadd2(acc0, acc1);
        acc2 = __hadd2(acc2, acc3);
        acc0 = __hadd2(acc0, acc2);
        float s = __low2float(acc0) + __high2float(acc0);

        float fcur = fA;
        fA = fB;
        if (t + 2 < S) fB = fb[(size_t)(t + 2) * L + c];   // prefetch

        if (smask[t]) {
            v = s * __expf(fcur);
            if ((t & 3) == 0) {   // uniform rescale by e[0], exactly accounted
                v *= __frcp_rn(e0f);
                offset += __logf(e0f);
            }
        }
        // else masked: alpha (v) carries over unchanged

        *(__nv_bfloat16*)(wb + 2 * c) = __float2bfloat16(v);
        __syncthreads();
    }

    // ---- denominator ----
    float contrib = v * __expf(endT[c]);
    #pragma unroll
    for (int o = 16; o; o >>= 1) contrib += __shfl_xor_sync(FULLMASK, contrib, o);
    if ((c & 31) == 0) sred[wid] = contrib;
    __syncthreads();
    float log_den = offset + __logf((sred[0] + sred[1]) + (sred[2] + sred[3]));
    __syncthreads();

    // ---- numerator: label-path score (exact fp32) ----
    float num = 0.f;
    float slf = 0.f;
    const int* lb = labels + b * S;
    for (int k = c; k < S; k += 128) {
        int mk = smask[k];
        slf += (float)mk;
        int lab = lb[k]; if (lab == -100) lab = 0;
        if (k == 0) {
            num += startT[lab] + fb[lab];
        } else if (mk) {
            int lp = lb[k - 1]; if (lp == -100) lp = 0;
            num += trans[lp * L + lab] + fb[(size_t)k * L + lab];
        }
    }
    #pragma unroll
    for (int o = 16; o; o >>= 1) {
        num += __shfl_xor_sync(FULLMASK, num, o);
        slf += __shfl_xor_sync(FULLMASK, slf, o);
    }
    if ((c & 31) == 0) { sred[wid] = num; sred[4 + wid] = slf; }
    __syncthreads();
    num = (sred[0] + sred[1]) + (sred[2] + sred[3]);
    slf = (sred[4] + sred[5]) + (sred[6] + sred[7]);

    int lastt = (int)(slf + 0.5f) - 1;
    if (lastt < 0) lastt = 0;
    int lastlab = lb[lastt]; if (lastlab == -100) lastlab = 0;
    num += endT[lastlab];

    if (c == 0) g_losses[b] = (log_den - num) * conf[b];
}

__global__ void k_finalize(float* __restrict__ out, int B) {
    int t = threadIdx.x;
    float x = (t < B) ? g_losses[t] : 0.f;
    #pragma unroll
    for (int o = 16; o; o >>= 1) x += __shfl_xor_sync(FULLMASK, x, o);
    __shared__ float sh[8];
    if ((t & 31) == 0) sh[t >> 5] = x;
    __syncthreads();
    if (t == 0) {
        float s = 0.f;
        int nw = (blockDim.x + 31) >> 5;
        for (int w = 0; w < nw; ++w) s += sh[w];
        out[0] = s / (float)B;
    }
}

extern "C" void kernel_launch(void* const* d_in, const int* in_sizes, int n_in,
                              void* d_out, int out_size) {
    const float* feats  = (const float*)d_in[0];
    const float* startT = (const float*)d_in[1];
    const float* endT   = (const float*)d_in[2];
    const float* trans  = (const float*)d_in[3];
    const float* conf   = (const float*)d_in[4];
    const int*   mask   = (const int*)  d_in[5];
    const int*   labels = (const int*)  d_in[6];

    const int B = in_sizes[4];            // 256
    const int S = in_sizes[5] / B;        // 512
    (void)n_in; (void)out_size;

    size_t smem = 512                     // double-buffered bf16 e vector
                + (size_t)S * 4           // mask
                + 32;                     // reduction scratch

    k_crf_forward<<<B, 128, smem>>>(feats, startT, endT, trans, conf,
                                    mask, labels, S);
    k_finalize<<<1, 256>>>((float*)d_out, B);
}